// round 17
// baseline (speedup 1.0000x reference)
#include <cuda_runtime.h>
#include <cstdint>

// CRF_76501957476894 — bidirectional CRF, 2 independent chains per warp.
// B=512, N=1024, K=64.  Z = alpha_512^T * E * c_513.
// CTA = 64 threads, handles batches (2c, 2c+1):
//   warp 0: FORWARD chains for both batches (shared col-major E packing)
//   warp 1: BACKWARD chains for both batches (shared row-major E packing)
// Two chains interleave in one warp -> chain latency of one hidden by the
// other's issue; ~1 warp/SMSP chip-wide. One __syncwarp per chain-step pair.
// Per chain: un-duplicated shared alpha (256B dbl buffer), 16 broadcast
// ld.shared.v2.b64, 8-way split f32x2 accumulators, renorm scale from first
// vector load's low word, log amortized every 2 steps.

#define FULLMASK 0xFFFFFFFFu

__device__ __forceinline__ unsigned long long pk2(float x, float y) {
    unsigned long long r;
    asm("mov.b64 %0, {%1, %2};" : "=l"(r) : "f"(x), "f"(y));
    return r;
}
__device__ __forceinline__ void upk2(unsigned long long p, float &x, float &y) {
    asm("mov.b64 {%0, %1}, %2;" : "=f"(x), "=f"(y) : "l"(p));
}
__device__ __forceinline__ float lo32(unsigned long long p) {
    float x, y;
    asm("mov.b64 {%0, %1}, %2;" : "=f"(x), "=f"(y) : "l"(p));
    (void)y;
    return x;
}

// One chain step, NO trailing syncwarp (caller syncs once per dual-step).
// 4-ull load granularity keeps live p-registers small for the dual version.
#define STEP_NS(EM0, EM1, RB, WB, ALO, AHI, PV, MM, DOLOG) do {                       \
    unsigned long long accA_[4] = {0ull,0ull,0ull,0ull};                              \
    unsigned long long accB_[4] = {0ull,0ull,0ull,0ull};                              \
    float vcur_, r_, em0r_, em1r_;                                                    \
    _Pragma("unroll")                                                                 \
    for (int h_ = 0; h_ < 4; h_++) {                                                  \
        _Pragma("unroll")                                                             \
        for (int q_ = 0; q_ < 2; q_++) {                                              \
            unsigned long long p_[4];                                                 \
            asm volatile("ld.shared.v2.b64 {%0,%1}, [%2];"                            \
                : "=l"(p_[0]), "=l"(p_[1]) : "r"((RB) + 64u*h_ + 32u*q_));            \
            asm volatile("ld.shared.v2.b64 {%0,%1}, [%2];"                            \
                : "=l"(p_[2]), "=l"(p_[3]) : "r"((RB) + 64u*h_ + 32u*q_ + 16u));      \
            if (h_ == 0 && q_ == 0) {                                                 \
                vcur_ = lo32(p_[0]);                                                  \
                asm("rcp.approx.f32 %0, %1;" : "=f"(r_) : "f"(vcur_));                \
                em0r_ = (EM0) * r_; em1r_ = (EM1) * r_;                               \
            }                                                                         \
            _Pragma("unroll")                                                         \
            for (int j_ = 0; j_ < 4; j_++) {                                          \
                asm("fma.rn.f32x2 %0, %1, %2, %0;"                                    \
                    : "+l"(accA_[h_]) : "l"(p_[j_]), "l"(EA[8*h_+4*q_+j_]));          \
                asm("fma.rn.f32x2 %0, %1, %2, %0;"                                    \
                    : "+l"(accB_[h_]) : "l"(p_[j_]), "l"(EB[8*h_+4*q_+j_]));          \
            }                                                                         \
        }                                                                             \
    }                                                                                 \
    PV *= vcur_;                                                                      \
    if (DOLOG) { MM += __logf(PV); PV = 1.0f; }                                       \
    unsigned long long A01_, A23_, P_, B01_, B23_, Q_;                                \
    asm("add.rn.f32x2 %0, %1, %2;" : "=l"(A01_) : "l"(accA_[0]), "l"(accA_[1]));      \
    asm("add.rn.f32x2 %0, %1, %2;" : "=l"(A23_) : "l"(accA_[2]), "l"(accA_[3]));      \
    asm("add.rn.f32x2 %0, %1, %2;" : "=l"(P_)   : "l"(A01_),     "l"(A23_));          \
    asm("add.rn.f32x2 %0, %1, %2;" : "=l"(B01_) : "l"(accB_[0]), "l"(accB_[1]));      \
    asm("add.rn.f32x2 %0, %1, %2;" : "=l"(B23_) : "l"(accB_[2]), "l"(accB_[3]));      \
    asm("add.rn.f32x2 %0, %1, %2;" : "=l"(Q_)   : "l"(B01_),     "l"(B23_));          \
    float p0_, p1_, q0_, q1_;                                                         \
    upk2(P_, p0_, p1_); upk2(Q_, q0_, q1_);                                           \
    ALO = (p0_ + p1_) * em0r_;                                                        \
    AHI = (q0_ + q1_) * em1r_;                                                        \
    asm volatile("st.shared.b64 [%0], %1;" :: "r"((WB) + 8u * l),                     \
                 "l"(pk2(ALO, AHI)));                                                 \
} while (0)

// Dual step k of a 2-step group: chain 0 (buffers A), chain 1 (buffers B).
#define STEP2(K, RA, WA, RBF, WBF, DOLOG) do {                                        \
    STEP_NS(ee0[0][K], ee1[0][K], RA,  WA,  alo0, ahi0, pv0, M0, DOLOG);              \
    STEP_NS(ee0[1][K], ee1[1][K], RBF, WBF, alo1, ahi1, pv1, M1, DOLOG);              \
    __syncwarp();                                                                     \
} while (0)

#define ROTATE_EE() do {                                                              \
    _Pragma("unroll")                                                                 \
    for (int c_ = 0; c_ < 2; c_++) {                                                  \
        ee0[c_][0]=en0[c_][0]; ee1[c_][0]=en1[c_][0];                                 \
        ee0[c_][1]=en0[c_][1]; ee1[c_][1]=en1[c_][1];                                 \
    }                                                                                 \
} while (0)

#define LOAD_TT(T, C, K) do {                                                         \
    raw[C][K]  = *reinterpret_cast<const float2*>(ypp[C] + (size_t)(T) * 64 + 2 * l); \
    yraw[C][K] = __ldg(yrr[C] + (T));                                                 \
} while (0)

#define PROC_FF(C, K, D0A, D1A) do {                                                  \
    int yv_ = yraw[C][K]; float2 ev_ = raw[C][K];                                     \
    pointv[C] += ((yv_ >> 1) == l) ? ((yv_ & 1) ? ev_.y : ev_.x) : 0.0f;              \
    tsv[C] += tsh[yprevv[C] * 64 + yv_];                                              \
    yprevv[C] = yv_;                                                                  \
    (D0A) = __expf(ev_.x); (D1A) = __expf(ev_.y);                                     \
} while (0)

#define PROC_BB(C, K, D0A, D1A) do {                                                  \
    int yv_ = yraw[C][K]; float2 ev_ = raw[C][K];                                     \
    pointv[C] += ((yv_ >> 1) == l) ? ((yv_ & 1) ? ev_.y : ev_.x) : 0.0f;              \
    tsv[C] += tsh[yv_ * 64 + yprevv[C]];                                              \
    yprevv[C] = yv_;                                                                  \
    (D0A) = __expf(ev_.x); (D1A) = __expf(ev_.y);                                     \
} while (0)

__global__ void __launch_bounds__(64) crf_fwd_kernel(
    const float* __restrict__ y_pred,   // [512,1024,64]
    const float* __restrict__ trans,    // [64,64]
    const int*   __restrict__ y_true,   // [512,1024]
    float*       __restrict__ out)      // [512]
{
    __shared__ float tsh[64 * 64];
    __shared__ unsigned long long abuf[2][2][2][32];  // [warp][chain][buf][lane]
    __shared__ unsigned long long resbuf[2][2][32];   // [warp][chain][lane]
    __shared__ float sM[2][2], sSc[2][2];

    const int tid = threadIdx.x;
    const int w = tid >> 5;          // 0 = fwd, 1 = bwd
    const int l = tid & 31;

    for (int i = tid; i < 4096; i += 64) tsh[i] = trans[i];
    __syncthreads();

    const int b0 = blockIdx.x * 2;
    const float* ypp[2] = { y_pred + (size_t)b0 * 65536,
                            y_pred + (size_t)(b0 + 1) * 65536 };
    const int*   yrr[2] = { y_true + b0 * 1024, y_true + (b0 + 1) * 1024 };

    // Shared E packing for BOTH chains of this warp (direction-dependent).
    unsigned long long EA[32], EB[32];
    #pragma unroll
    for (int s = 0; s < 32; s++) {
        if (w == 0) {   // fwd: column pairs
            EA[s] = pk2(__expf(tsh[(2*s)*64 + 2*l]),   __expf(tsh[(2*s+1)*64 + 2*l]));
            EB[s] = pk2(__expf(tsh[(2*s)*64 + 2*l+1]), __expf(tsh[(2*s+1)*64 + 2*l+1]));
        } else {        // bwd: row pairs
            EA[s] = pk2(__expf(tsh[(2*l)*64 + 2*s]),   __expf(tsh[(2*l)*64 + 2*s+1]));
            EB[s] = pk2(__expf(tsh[(2*l+1)*64 + 2*s]), __expf(tsh[(2*l+1)*64 + 2*s+1]));
        }
    }

    const uint32_t a0b0 = (uint32_t)__cvta_generic_to_shared(&abuf[w][0][0][0]);
    const uint32_t a0b1 = a0b0 + 256u;
    const uint32_t a1b0 = (uint32_t)__cvta_generic_to_shared(&abuf[w][1][0][0]);
    const uint32_t a1b1 = a1b0 + 256u;

    float pointv[2], tsv[2] = {0.0f, 0.0f};
    int   yprevv[2];
    float alo0, ahi0, alo1, ahi1;
    float M0 = 0.0f, M1 = 0.0f, pv0 = 1.0f, pv1 = 1.0f;
    float2 raw[2][2];
    int    yraw[2][2];
    float  ee0[2][2], ee1[2][2], en0[2][2], en1[2][2];

    if (w == 0) {
        // ---------------- FORWARD: t = 0..512 + 1 plain matvec ----------------
        #pragma unroll
        for (int c = 0; c < 2; c++) {
            float2 e0 = *reinterpret_cast<const float2*>(ypp[c] + 2 * l);
            int y0 = __ldg(yrr[c]);
            pointv[c] = ((y0 >> 1) == l) ? ((y0 & 1) ? e0.y : e0.x) : 0.0f;
            yprevv[c] = y0;
            float la = __expf(e0.x), ha = __expf(e0.y);
            if (c == 0) { alo0 = la; ahi0 = ha; }
            else        { alo1 = la; ahi1 = ha; }
            uint32_t dst = (c == 0 ? a0b0 : a1b0) + 8u * l;
            asm volatile("st.shared.b64 [%0], %1;" :: "r"(dst), "l"(pk2(la, ha)));
        }
        __syncwarp();

        // Groups of 2: Gk covers t = 1+2k, 2+2k (k = 0..255).
        #pragma unroll
        for (int c = 0; c < 2; c++) { LOAD_TT(1, c, 0); LOAD_TT(2, c, 1); }
        #pragma unroll
        for (int c = 0; c < 2; c++) {
            PROC_FF(c, 0, ee0[c][0], ee1[c][0]);
            PROC_FF(c, 1, ee0[c][1], ee1[c][1]);
        }
        #pragma unroll
        for (int c = 0; c < 2; c++) { LOAD_TT(3, c, 0); LOAD_TT(4, c, 1); }

        // Loop g = 0..253: step G_g; proc G_{g+1}; load G_{g+2} (max t = 512).
        #pragma unroll 1
        for (int g = 0; g < 254; ++g) {
            #pragma unroll
            for (int c = 0; c < 2; c++) {
                PROC_FF(c, 0, en0[c][0], en1[c][0]);
                PROC_FF(c, 1, en0[c][1], en1[c][1]);
            }
            const int tb = 5 + 2 * g;
            #pragma unroll
            for (int c = 0; c < 2; c++) { LOAD_TT(tb, c, 0); LOAD_TT(tb + 1, c, 1); }
            STEP2(0, a0b0, a0b1, a1b0, a1b1, false);
            STEP2(1, a0b1, a0b0, a1b1, a1b0, true);
            ROTATE_EE();
        }
        // ee = G254 (t=509,510); raw = G255 loads (t=511,512).
        #pragma unroll
        for (int c = 0; c < 2; c++) {
            PROC_FF(c, 0, en0[c][0], en1[c][0]);
            PROC_FF(c, 1, en0[c][1], en1[c][1]);
        }
        STEP2(0, a0b0, a0b1, a1b0, a1b1, false);   // t = 509
        STEP2(1, a0b1, a0b0, a1b1, a1b0, true);    // t = 510
        ROTATE_EE();                               // ee <- G255
        STEP2(0, a0b0, a0b1, a1b0, a1b1, false);   // t = 511
        STEP2(1, a0b1, a0b0, a1b1, a1b0, true);    // t = 512 -> alpha_512 in buf0
        // d = alpha_512^T E (em = 1), reads buf0:
        STEP_NS(1.0f, 1.0f, a0b0, a0b1, alo0, ahi0, pv0, M0, false);
        STEP_NS(1.0f, 1.0f, a1b0, a1b1, alo1, ahi1, pv1, M1, false);
    } else {
        // ---------------- BACKWARD: t = 1022..513; c_1023 = em_1023 ----------------
        #pragma unroll
        for (int c = 0; c < 2; c++) {
            float2 e0 = *reinterpret_cast<const float2*>(ypp[c] + (size_t)1023*64 + 2*l);
            int y0 = __ldg(yrr[c] + 1023);
            pointv[c] = ((y0 >> 1) == l) ? ((y0 & 1) ? e0.y : e0.x) : 0.0f;
            yprevv[c] = y0;
            float la = __expf(e0.x), ha = __expf(e0.y);
            if (c == 0) { alo0 = la; ahi0 = ha; }
            else        { alo1 = la; ahi1 = ha; }
            uint32_t dst = (c == 0 ? a0b0 : a1b0) + 8u * l;
            asm volatile("st.shared.b64 [%0], %1;" :: "r"(dst), "l"(pk2(la, ha)));
        }
        __syncwarp();

        // Groups of 2: Gk covers t = 1022-2k, 1021-2k (k = 0..254).
        #pragma unroll
        for (int c = 0; c < 2; c++) { LOAD_TT(1022, c, 0); LOAD_TT(1021, c, 1); }
        #pragma unroll
        for (int c = 0; c < 2; c++) {
            PROC_BB(c, 0, ee0[c][0], ee1[c][0]);
            PROC_BB(c, 1, ee0[c][1], ee1[c][1]);
        }
        #pragma unroll
        for (int c = 0; c < 2; c++) { LOAD_TT(1020, c, 0); LOAD_TT(1019, c, 1); }

        // Loop g = 0..252: step G_g; proc G_{g+1}; load G_{g+2} (min t = 513).
        #pragma unroll 1
        for (int g = 0; g < 253; ++g) {
            #pragma unroll
            for (int c = 0; c < 2; c++) {
                PROC_BB(c, 0, en0[c][0], en1[c][0]);
                PROC_BB(c, 1, en0[c][1], en1[c][1]);
            }
            const int tb = 1018 - 2 * g;
            #pragma unroll
            for (int c = 0; c < 2; c++) { LOAD_TT(tb, c, 0); LOAD_TT(tb - 1, c, 1); }
            STEP2(0, a0b0, a0b1, a1b0, a1b1, false);
            STEP2(1, a0b1, a0b0, a1b1, a1b0, true);
            ROTATE_EE();
        }
        // ee = G253 (t=516,515); raw = G254 loads (t=514,513).
        #pragma unroll
        for (int c = 0; c < 2; c++) {
            PROC_BB(c, 0, en0[c][0], en1[c][0]);
            PROC_BB(c, 1, en0[c][1], en1[c][1]);
        }
        STEP2(0, a0b0, a0b1, a1b0, a1b1, false);   // t = 516
        STEP2(1, a0b1, a0b0, a1b1, a1b0, true);    // t = 515
        ROTATE_EE();                               // ee <- G254
        STEP2(0, a0b0, a0b1, a1b0, a1b1, false);   // t = 514
        STEP2(1, a0b1, a0b0, a1b1, a1b0, true);    // t = 513 -> c_513 in regs
        // patch transition (y_512, y_513); yprevv[c] == y_513 here.
        #pragma unroll
        for (int c = 0; c < 2; c++) {
            int y512 = __ldg(yrr[c] + 512);
            tsv[c] += tsh[y512 * 64 + yprevv[c]];
        }
    }

    // ---- per-warp wrap-up (both chains) ----
    M0 += __logf(pv0);
    M1 += __logf(pv1);
    #pragma unroll
    for (int o = 16; o > 0; o >>= 1) pointv[0] += __shfl_xor_sync(FULLMASK, pointv[0], o);
    #pragma unroll
    for (int o = 16; o > 0; o >>= 1) pointv[1] += __shfl_xor_sync(FULLMASK, pointv[1], o);
    if (l == 0) {
        sM[w][0] = M0;  sSc[w][0] = pointv[0] + tsv[0];
        sM[w][1] = M1;  sSc[w][1] = pointv[1] + tsv[1];
    }
    resbuf[w][0][l] = pk2(alo0, ahi0);
    resbuf[w][1][l] = pk2(alo1, ahi1);
    __syncthreads();

    // ---- combine (warp 0): loss_c = M_f + M_b + log(d.c) - scores ----
    if (w == 0) {
        #pragma unroll
        for (int c = 0; c < 2; c++) {
            float dlo = (c == 0) ? alo0 : alo1;
            float dhi = (c == 0) ? ahi0 : ahi1;
            float clo, chi;
            upk2(resbuf[1][c][l], clo, chi);
            float prod = dlo * clo + dhi * chi;
            #pragma unroll
            for (int o = 16; o > 0; o >>= 1) prod += __shfl_xor_sync(FULLMASK, prod, o);
            if (l == 0)
                out[b0 + c] = (sM[0][c] + sM[1][c] + __logf(prod))
                            - (sSc[0][c] + sSc[1][c]);
        }
    }
}

extern "C" void kernel_launch(void* const* d_in, const int* in_sizes, int n_in,
                              void* d_out, int out_size) {
    const float* y_pred = (const float*)d_in[0];   // [512,1024,64] f32
    const float* trans  = (const float*)d_in[1];   // [64,64] f32
    const int*   y_true = (const int*)d_in[2];     // [512,1024] i32
    float* out = (float*)d_out;                    // [512] f32
    (void)in_sizes; (void)n_in; (void)out_size;
    crf_fwd_kernel<<<256, 64>>>(y_pred, trans, y_true, out);
}